// round 1
// baseline (speedup 1.0000x reference)
#include <cuda_runtime.h>

// Shapes (fixed for this problem)
static constexpr int BATCH = 2048;   // B
static constexpr int NODES = 128;    // M
static constexpr int DIM   = 512;    // D == H
static constexpr int KX    = 2048;   // packed X columns: [img_mean|txt_mean|it|ii]

// Scratch (static __device__ globals — allocation-free per harness rules)
__device__ float g_X[(size_t)BATCH * KX];      // 16 MB
__device__ float g_Wcomb[DIM * 1024];          // 2 MB: (W_r_img+W_r_txt) @ W_user
__device__ float g_bcomb[DIM];

// ---------------------------------------------------------------------------
// Kernel 1: W_comb[n,k] = sum_h (W_r_img[n,h]+W_r_txt[n,h]) * W_user[h,k]
// M'=512 (n), N'=1024 (k), K'=512 (h). 64x64x16 tiles, 256 thr, 4x4/thread.
// ---------------------------------------------------------------------------
__global__ void __launch_bounds__(256) k_wcomb(
    const float* __restrict__ Wri, const float* __restrict__ Wrt,
    const float* __restrict__ Wu)
{
    __shared__ float As[16][68];   // transposed A tile (pad to soften STS conflicts)
    __shared__ float Bs[16][64];   // B tile direct (h-outer layout)
    const int tid = threadIdx.x;
    const int n0  = blockIdx.x * 64;   // k-dim (0..1023)
    const int m0  = blockIdx.y * 64;   // n'-rows (0..511)
    const int tx = tid & 15, ty = tid >> 4;
    const int arow = tid >> 2, ac = (tid & 3) * 4;   // A tile: 64 rows x 16 h
    const int brow = tid >> 4, bc = (tid & 15) * 4;  // B tile: 16 h  x 64 k

    float acc[4][4] = {};
    float4 ra, rb;
    {
        float4 x = *reinterpret_cast<const float4*>(Wri + (m0 + arow) * 512 + ac);
        float4 y = *reinterpret_cast<const float4*>(Wrt + (m0 + arow) * 512 + ac);
        ra = make_float4(x.x + y.x, x.y + y.y, x.z + y.z, x.w + y.w);
        rb = *reinterpret_cast<const float4*>(Wu + brow * 1024 + n0 + bc);
    }
    for (int kt = 0; kt < 32; ++kt) {
        As[ac + 0][arow] = ra.x; As[ac + 1][arow] = ra.y;
        As[ac + 2][arow] = ra.z; As[ac + 3][arow] = ra.w;
        *reinterpret_cast<float4*>(&Bs[brow][bc]) = rb;
        __syncthreads();
        if (kt < 31) {
            const int h0 = (kt + 1) * 16;
            float4 x = *reinterpret_cast<const float4*>(Wri + (m0 + arow) * 512 + h0 + ac);
            float4 y = *reinterpret_cast<const float4*>(Wrt + (m0 + arow) * 512 + h0 + ac);
            ra = make_float4(x.x + y.x, x.y + y.y, x.z + y.z, x.w + y.w);
            rb = *reinterpret_cast<const float4*>(Wu + (h0 + brow) * 1024 + n0 + bc);
        }
        #pragma unroll
        for (int kk = 0; kk < 16; ++kk) {
            float4 a = *reinterpret_cast<const float4*>(&As[kk][ty * 4]);
            float4 b = *reinterpret_cast<const float4*>(&Bs[kk][tx * 4]);
            acc[0][0] += a.x * b.x; acc[0][1] += a.x * b.y; acc[0][2] += a.x * b.z; acc[0][3] += a.x * b.w;
            acc[1][0] += a.y * b.x; acc[1][1] += a.y * b.y; acc[1][2] += a.y * b.z; acc[1][3] += a.y * b.w;
            acc[2][0] += a.z * b.x; acc[2][1] += a.z * b.y; acc[2][2] += a.z * b.z; acc[2][3] += a.z * b.w;
            acc[3][0] += a.w * b.x; acc[3][1] += a.w * b.y; acc[3][2] += a.w * b.z; acc[3][3] += a.w * b.w;
        }
        __syncthreads();
    }
    #pragma unroll
    for (int r = 0; r < 4; ++r) {
        float4 o = make_float4(acc[r][0], acc[r][1], acc[r][2], acc[r][3]);
        *reinterpret_cast<float4*>(g_Wcomb + (m0 + ty * 4 + r) * 1024 + n0 + tx * 4) = o;
    }
}

// ---------------------------------------------------------------------------
// Kernel 2: b_comb[n] = b_l_img[n] + b_l_txt[n] + sum_h (Wr_img+Wr_txt)[n,h]*b_user[h]
// ---------------------------------------------------------------------------
__global__ void __launch_bounds__(256) k_bcomb(
    const float* __restrict__ Wri, const float* __restrict__ Wrt,
    const float* __restrict__ bu,  const float* __restrict__ bli,
    const float* __restrict__ blt)
{
    __shared__ float bs[512];
    const int tid = threadIdx.x;
    bs[tid] = bu[tid];
    bs[tid + 256] = bu[tid + 256];
    __syncthreads();
    const int n = blockIdx.x * 256 + tid;
    const float4* p1 = reinterpret_cast<const float4*>(Wri + n * 512);
    const float4* p2 = reinterpret_cast<const float4*>(Wrt + n * 512);
    float acc = 0.f;
    #pragma unroll 4
    for (int h4 = 0; h4 < 128; ++h4) {
        float4 a = p1[h4], b = p2[h4];
        const float* bb = bs + h4 * 4;
        acc += (a.x + b.x) * bb[0] + (a.y + b.y) * bb[1]
             + (a.z + b.z) * bb[2] + (a.w + b.w) * bb[3];
    }
    g_bcomb[n] = acc + bli[n] + blt[n];
}

// ---------------------------------------------------------------------------
// Kernel 3: stream means + pack X rows. HBM-bound (reads 1.07 GB).
// One CTA per batch row; warps 0-3 -> img mean, warps 4-7 -> txt mean.
// ---------------------------------------------------------------------------
__global__ void __launch_bounds__(256) k_mean_pack(
    const float* __restrict__ itex, const float* __restrict__ iimg,
    const float* __restrict__ btxt, const float* __restrict__ bimg)
{
    const int b = blockIdx.x;
    const int t = threadIdx.x;
    float* Xrow = g_X + (size_t)b * KX;

    const bool lo = (t < 128);
    const float* src = lo ? bimg : btxt;
    const int chunk  = lo ? t : (t - 128);   // float4 chunk over H=512 -> 128 chunks
    const int xoff   = lo ? 0 : 512;

    const float4* p = reinterpret_cast<const float4*>(src + (size_t)b * NODES * DIM) + chunk;
    float4 acc = make_float4(0.f, 0.f, 0.f, 0.f);
    #pragma unroll 8
    for (int m = 0; m < NODES; ++m) {
        float4 v = p[(size_t)m * (DIM / 4)];
        acc.x += v.x; acc.y += v.y; acc.z += v.z; acc.w += v.w;
    }
    const float s = 1.0f / (float)NODES;
    acc.x *= s; acc.y *= s; acc.z *= s; acc.w *= s;
    reinterpret_cast<float4*>(Xrow + xoff)[chunk] = acc;

    // passthrough: X[b,1024:1536)=input_text[b], X[b,1536:2048)=input_img[b]
    const float* src2 = lo ? itex : iimg;
    const int xoff2   = lo ? 1024 : 1536;
    reinterpret_cast<float4*>(Xrow + xoff2)[chunk] =
        reinterpret_cast<const float4*>(src2 + (size_t)b * DIM)[chunk];
}

// ---------------------------------------------------------------------------
// Kernel 4: out = relu(X @ W_all^T + b_comb)
// M=2048, N=512, K=2048. W_all rows come from 3 sources selected per k-tile:
//   k in [0,512)     -> W_l_img   (ld 512)
//   k in [512,1024)  -> W_l_txt   (ld 512)
//   k in [1024,2048) -> g_Wcomb   (ld 1024)
// 64x64x16 tiles, 256 thr, 4x4/thread, register-double-buffered globals.
// ---------------------------------------------------------------------------
__global__ void __launch_bounds__(256) k_gemm(
    const float* __restrict__ Wli, const float* __restrict__ Wlt,
    float* __restrict__ out)
{
    __shared__ float As[16][68];
    __shared__ float Ws[16][68];
    const int tid = threadIdx.x;
    const int n0  = blockIdx.x * 64;   // over H=512
    const int m0  = blockIdx.y * 64;   // over B=2048
    const int tx = tid & 15, ty = tid >> 4;
    const int lrow = tid >> 2, lc = (tid & 3) * 4;  // both tiles: 64 rows x 16 k

    float acc[4][4] = {};

    auto loadW = [&](int k0) -> float4 {
        const float* base; int ld, off;
        if (k0 < 512)       { base = Wli;     ld = 512;  off = k0; }
        else if (k0 < 1024) { base = Wlt;     ld = 512;  off = k0 - 512; }
        else                { base = g_Wcomb; ld = 1024; off = k0 - 1024; }
        return *reinterpret_cast<const float4*>(base + (n0 + lrow) * ld + off + lc);
    };

    float4 ra = *reinterpret_cast<const float4*>(g_X + (size_t)(m0 + lrow) * KX + lc);
    float4 rw = loadW(0);

    for (int kt = 0; kt < KX / 16; ++kt) {
        As[lc + 0][lrow] = ra.x; As[lc + 1][lrow] = ra.y;
        As[lc + 2][lrow] = ra.z; As[lc + 3][lrow] = ra.w;
        Ws[lc + 0][lrow] = rw.x; Ws[lc + 1][lrow] = rw.y;
        Ws[lc + 2][lrow] = rw.z; Ws[lc + 3][lrow] = rw.w;
        __syncthreads();
        if (kt < KX / 16 - 1) {
            const int k0 = (kt + 1) * 16;
            ra = *reinterpret_cast<const float4*>(g_X + (size_t)(m0 + lrow) * KX + k0 + lc);
            rw = loadW(k0);
        }
        #pragma unroll
        for (int kk = 0; kk < 16; ++kk) {
            float4 a = *reinterpret_cast<const float4*>(&As[kk][ty * 4]);
            float4 w = *reinterpret_cast<const float4*>(&Ws[kk][tx * 4]);
            acc[0][0] += a.x * w.x; acc[0][1] += a.x * w.y; acc[0][2] += a.x * w.z; acc[0][3] += a.x * w.w;
            acc[1][0] += a.y * w.x; acc[1][1] += a.y * w.y; acc[1][2] += a.y * w.z; acc[1][3] += a.y * w.w;
            acc[2][0] += a.z * w.x; acc[2][1] += a.z * w.y; acc[2][2] += a.z * w.z; acc[2][3] += a.z * w.w;
            acc[3][0] += a.w * w.x; acc[3][1] += a.w * w.y; acc[3][2] += a.w * w.z; acc[3][3] += a.w * w.w;
        }
        __syncthreads();
    }

    const float4 bc = *reinterpret_cast<const float4*>(g_bcomb + n0 + tx * 4);
    #pragma unroll
    for (int r = 0; r < 4; ++r) {
        float4 o;
        o.x = fmaxf(acc[r][0] + bc.x, 0.f);
        o.y = fmaxf(acc[r][1] + bc.y, 0.f);
        o.z = fmaxf(acc[r][2] + bc.z, 0.f);
        o.w = fmaxf(acc[r][3] + bc.w, 0.f);
        *reinterpret_cast<float4*>(out + (size_t)(m0 + ty * 4 + r) * DIM + n0 + tx * 4) = o;
    }
}

// ---------------------------------------------------------------------------
extern "C" void kernel_launch(void* const* d_in, const int* in_sizes, int n_in,
                              void* d_out, int out_size)
{
    const float* input_text = (const float*)d_in[0];
    const float* input_img  = (const float*)d_in[1];
    const float* btxt       = (const float*)d_in[2];
    const float* bimg       = (const float*)d_in[3];
    const float* W_user     = (const float*)d_in[4];
    const float* b_user     = (const float*)d_in[5];
    const float* W_l_img    = (const float*)d_in[6];
    const float* b_l_img    = (const float*)d_in[7];
    const float* W_r_img    = (const float*)d_in[8];
    const float* W_l_txt    = (const float*)d_in[9];
    const float* b_l_txt    = (const float*)d_in[10];
    const float* W_r_txt    = (const float*)d_in[11];
    float* out = (float*)d_out;

    k_wcomb<<<dim3(16, 8), 256>>>(W_r_img, W_r_txt, W_user);
    k_bcomb<<<2, 256>>>(W_r_img, W_r_txt, b_user, b_l_img, b_l_txt);
    k_mean_pack<<<BATCH, 256>>>(input_text, input_img, btxt, bimg);
    k_gemm<<<dim3(DIM / 64, BATCH / 64), 256>>>(W_l_img, W_l_txt, out);
}

// round 2
// speedup vs baseline: 1.4685x; 1.4685x over previous
#include <cuda_runtime.h>
#include <cuda_bf16.h>
#include <cstdint>

static constexpr int BATCH = 2048;   // B
static constexpr int NODES = 128;    // M
static constexpr int DIM   = 512;    // D == H
static constexpr int KX    = 2048;   // packed X cols: [img_mean|txt_mean|it|ii]

// Scratch (static __device__ globals — allocation-free)
__device__ __nv_bfloat16 g_Xhi[(size_t)BATCH * KX];   // 8 MB
__device__ __nv_bfloat16 g_Xlo[(size_t)BATCH * KX];   // 8 MB
__device__ __nv_bfloat16 g_Whi[(size_t)DIM * KX];     // 2 MB
__device__ __nv_bfloat16 g_Wlo[(size_t)DIM * KX];     // 2 MB
__device__ float g_Wcomb[DIM * 1024];                 // (W_r_img+W_r_txt) @ W_user
__device__ float g_bcomb[DIM];

// ---------------------------------------------------------------------------
// helpers
// ---------------------------------------------------------------------------
__device__ __forceinline__ void split_store4(__nv_bfloat16* hiP, __nv_bfloat16* loP,
                                             size_t idx, float4 v)
{
    union U { __nv_bfloat16 b[4]; uint2 u; } hu, lu;
    float f[4] = {v.x, v.y, v.z, v.w};
    #pragma unroll
    for (int i = 0; i < 4; ++i) {
        __nv_bfloat16 h = __float2bfloat16(f[i]);
        hu.b[i] = h;
        lu.b[i] = __float2bfloat16(f[i] - __bfloat162float(h));
    }
    *reinterpret_cast<uint2*>(hiP + idx) = hu.u;
    *reinterpret_cast<uint2*>(loP + idx) = lu.u;
}

__device__ __forceinline__ uint32_t sw_off(int r, int c) {
    // 32-bf16 rows (64B); 16B chunk swizzle: c' = c ^ ((r>>1)&3)
    return (uint32_t)(r * 64 + ((c ^ ((r >> 1) & 3)) << 4));
}

__device__ __forceinline__ void cp_async16(uint32_t dst, const void* src) {
    asm volatile("cp.async.cg.shared.global [%0], [%1], 16;\n" :: "r"(dst), "l"(src));
}
__device__ __forceinline__ void cp_commit() { asm volatile("cp.async.commit_group;\n"); }
__device__ __forceinline__ void cp_wait1()  { asm volatile("cp.async.wait_group 1;\n"); }

__device__ __forceinline__ void ldsm4(uint32_t* r, uint32_t addr) {
    asm volatile("ldmatrix.sync.aligned.m8n8.x4.shared.b16 {%0,%1,%2,%3}, [%4];\n"
                 : "=r"(r[0]), "=r"(r[1]), "=r"(r[2]), "=r"(r[3]) : "r"(addr));
}
__device__ __forceinline__ void mma16816(float* c, const uint32_t* a, const uint32_t* b) {
    asm volatile("mma.sync.aligned.m16n8k16.row.col.f32.bf16.bf16.f32 "
                 "{%0,%1,%2,%3}, {%4,%5,%6,%7}, {%8,%9}, {%0,%1,%2,%3};\n"
                 : "+f"(c[0]), "+f"(c[1]), "+f"(c[2]), "+f"(c[3])
                 : "r"(a[0]), "r"(a[1]), "r"(a[2]), "r"(a[3]), "r"(b[0]), "r"(b[1]));
}

// ---------------------------------------------------------------------------
// Kernel 1 (fused): blockIdx.x in
//   [0, 2048)      : mean+pack  (HBM stream)
//   [2048, 2176)   : W_comb = (W_r_img+W_r_txt) @ W_user     (fp32 SIMT GEMM)
//   [2176, 2178)   : b_comb
// ---------------------------------------------------------------------------
__global__ void __launch_bounds__(256) k_pre(
    const float* __restrict__ itex, const float* __restrict__ iimg,
    const float* __restrict__ btxt, const float* __restrict__ bimg,
    const float* __restrict__ Wri,  const float* __restrict__ Wrt,
    const float* __restrict__ Wu,   const float* __restrict__ bu,
    const float* __restrict__ bli,  const float* __restrict__ blt)
{
    __shared__ float As[16][68];
    __shared__ float Bs[16][64];

    const int bx = blockIdx.x;
    const int tid = threadIdx.x;

    if (bx < 2048) {
        // ---- mean + pack (bf16 hi/lo) ----
        const int b = bx;
        const bool lo = (tid < 128);
        const float* src = lo ? bimg : btxt;
        const int chunk  = lo ? tid : (tid - 128);      // float4 chunk over H=512
        const int xoff   = lo ? 0 : 512;

        const float4* p = reinterpret_cast<const float4*>(src + (size_t)b * NODES * DIM) + chunk;
        float4 acc = make_float4(0.f, 0.f, 0.f, 0.f);
        #pragma unroll 16
        for (int m = 0; m < NODES; ++m) {
            float4 v = __ldcs(p + (size_t)m * (DIM / 4));
            acc.x += v.x; acc.y += v.y; acc.z += v.z; acc.w += v.w;
        }
        const float s = 1.0f / (float)NODES;
        acc.x *= s; acc.y *= s; acc.z *= s; acc.w *= s;
        split_store4(g_Xhi, g_Xlo, (size_t)b * KX + xoff + chunk * 4, acc);

        const float* src2 = lo ? itex : iimg;
        const int xoff2   = lo ? 1024 : 1536;
        float4 pv = reinterpret_cast<const float4*>(src2 + (size_t)b * DIM)[chunk];
        split_store4(g_Xhi, g_Xlo, (size_t)b * KX + xoff2 + chunk * 4, pv);
        return;
    }

    if (bx < 2176) {
        // ---- W_comb GEMM: [512 x 1024] = (Wri+Wrt)[512x512] @ Wu[512x1024] ----
        const int r  = bx - 2048;
        const int n0 = (r & 15) * 64;     // over 1024 cols
        const int m0 = (r >> 4) * 64;     // over 512 rows
        const int tx = tid & 15, ty = tid >> 4;
        const int arow = tid >> 2, ac = (tid & 3) * 4;
        const int brow = tid >> 4, bc = (tid & 15) * 4;

        float acc[4][4] = {};
        float4 ra, rb;
        {
            float4 x = *reinterpret_cast<const float4*>(Wri + (m0 + arow) * 512 + ac);
            float4 y = *reinterpret_cast<const float4*>(Wrt + (m0 + arow) * 512 + ac);
            ra = make_float4(x.x + y.x, x.y + y.y, x.z + y.z, x.w + y.w);
            rb = *reinterpret_cast<const float4*>(Wu + brow * 1024 + n0 + bc);
        }
        for (int kt = 0; kt < 32; ++kt) {
            As[ac + 0][arow] = ra.x; As[ac + 1][arow] = ra.y;
            As[ac + 2][arow] = ra.z; As[ac + 3][arow] = ra.w;
            *reinterpret_cast<float4*>(&Bs[brow][bc]) = rb;
            __syncthreads();
            if (kt < 31) {
                const int h0 = (kt + 1) * 16;
                float4 x = *reinterpret_cast<const float4*>(Wri + (m0 + arow) * 512 + h0 + ac);
                float4 y = *reinterpret_cast<const float4*>(Wrt + (m0 + arow) * 512 + h0 + ac);
                ra = make_float4(x.x + y.x, x.y + y.y, x.z + y.z, x.w + y.w);
                rb = *reinterpret_cast<const float4*>(Wu + (h0 + brow) * 1024 + n0 + bc);
            }
            #pragma unroll
            for (int kk = 0; kk < 16; ++kk) {
                float4 a = *reinterpret_cast<const float4*>(&As[kk][ty * 4]);
                float4 b = *reinterpret_cast<const float4*>(&Bs[kk][tx * 4]);
                acc[0][0] += a.x*b.x; acc[0][1] += a.x*b.y; acc[0][2] += a.x*b.z; acc[0][3] += a.x*b.w;
                acc[1][0] += a.y*b.x; acc[1][1] += a.y*b.y; acc[1][2] += a.y*b.z; acc[1][3] += a.y*b.w;
                acc[2][0] += a.z*b.x; acc[2][1] += a.z*b.y; acc[2][2] += a.z*b.z; acc[2][3] += a.z*b.w;
                acc[3][0] += a.w*b.x; acc[3][1] += a.w*b.y; acc[3][2] += a.w*b.z; acc[3][3] += a.w*b.w;
            }
            __syncthreads();
        }
        #pragma unroll
        for (int rr = 0; rr < 4; ++rr) {
            float4 o = make_float4(acc[rr][0], acc[rr][1], acc[rr][2], acc[rr][3]);
            *reinterpret_cast<float4*>(g_Wcomb + (m0 + ty * 4 + rr) * 1024 + n0 + tx * 4) = o;
        }
        return;
    }

    {
        // ---- b_comb ----
        __shared__ float bs[512];
        bs[tid] = bu[tid];
        bs[tid + 256] = bu[tid + 256];
        __syncthreads();
        const int n = (bx - 2176) * 256 + tid;
        const float4* p1 = reinterpret_cast<const float4*>(Wri + n * 512);
        const float4* p2 = reinterpret_cast<const float4*>(Wrt + n * 512);
        float acc = 0.f;
        #pragma unroll 4
        for (int h4 = 0; h4 < 128; ++h4) {
            float4 a = p1[h4], b = p2[h4];
            const float* bb = bs + h4 * 4;
            acc += (a.x + b.x) * bb[0] + (a.y + b.y) * bb[1]
                 + (a.z + b.z) * bb[2] + (a.w + b.w) * bb[3];
        }
        g_bcomb[n] = acc + bli[n] + blt[n];
    }
}

// ---------------------------------------------------------------------------
// Kernel 2: pack W_all = [W_l_img | W_l_txt | W_comb] into bf16 hi/lo [512][2048]
// ---------------------------------------------------------------------------
__global__ void __launch_bounds__(256) k_wpack(
    const float* __restrict__ Wli, const float* __restrict__ Wlt)
{
    const int id = blockIdx.x * 256 + threadIdx.x;   // 262144 float4s
    const int n  = id >> 9;
    const int k  = (id & 511) * 4;
    float4 v;
    if (k < 512)        v = *reinterpret_cast<const float4*>(Wli + n * 512 + k);
    else if (k < 1024)  v = *reinterpret_cast<const float4*>(Wlt + n * 512 + (k - 512));
    else                v = *reinterpret_cast<const float4*>(g_Wcomb + n * 1024 + (k - 1024));
    split_store4(g_Whi, g_Wlo, (size_t)n * KX + k, v);
}

// ---------------------------------------------------------------------------
// Kernel 3: out = relu(X @ W_all^T + b_comb), bf16 3-term split, tensor cores.
// CTA 128(M) x 64(N), KBLK=32, 8 warps (4m x 2n), warp tile 32x32.
// M=2048, N=512, K=2048 -> grid (8, 16) = 128 CTAs.
// ---------------------------------------------------------------------------
__global__ void __launch_bounds__(256) k_gemm_tc(float* __restrict__ out)
{
    // SMEM: 2-stage: Ahi 2x8KB | Alo 2x8KB | Bhi 2x4KB | Blo 2x4KB = 48KB
    __shared__ __align__(128) unsigned char sm[49152];
    const uint32_t smBase = (uint32_t)__cvta_generic_to_shared(sm);
    const uint32_t A_HI = smBase, A_LO = smBase + 16384;
    const uint32_t B_HI = smBase + 32768, B_LO = smBase + 40960;

    const int tid = threadIdx.x;
    const int l   = tid & 31;
    const int wid = tid >> 5;
    const int wm  = wid >> 1;            // 0..3 -> m offset wm*32
    const int wn  = wid & 1;             // 0..1 -> n offset wn*32
    const int n0  = blockIdx.x * 64;
    const int m0  = blockIdx.y * 128;

    // precompute ldmatrix offsets (relative to stage base)
    uint32_t offA[2][2], offB[2][2];
    {
        const int ti = l >> 3;
        #pragma unroll
        for (int f = 0; f < 2; ++f)
            #pragma unroll
            for (int ks = 0; ks < 2; ++ks) {
                int tm = wm * 32 + f * 16 + (ti & 1) * 8 + (l & 7);
                int tc = ks * 2 + (ti >> 1);
                offA[f][ks] = (uint32_t)(tm * 64 + ((tc ^ ((tm >> 1) & 3)) << 4));
            }
        #pragma unroll
        for (int q = 0; q < 2; ++q)
            #pragma unroll
            for (int ks = 0; ks < 2; ++ks) {
                int tn = wn * 32 + q * 16 + (ti >> 1) * 8 + (l & 7);
                int tc = ks * 2 + (ti & 1);
                offB[q][ks] = (uint32_t)(tn * 64 + ((tc ^ ((tn >> 1) & 3)) << 4));
            }
    }

    // per-thread load assignments
    const int ar0 = tid >> 2,           ac0 = tid & 3;          // A chunk (rep 0)
    const int ar1 = (tid + 256) >> 2,   ac1 = tid & 3;          // A chunk (rep 1)
    const int br  = tid >> 2,           bcc = tid & 3;          // B chunk

    auto load_stage = [&](int s, int kb) {
        const uint32_t aHi = A_HI + s * 8192, aLo = A_LO + s * 8192;
        const uint32_t bHi = B_HI + s * 4096, bLo = B_LO + s * 4096;
        cp_async16(aHi + sw_off(ar0, ac0), g_Xhi + (size_t)(m0 + ar0) * KX + kb + ac0 * 8);
        cp_async16(aLo + sw_off(ar0, ac0), g_Xlo + (size_t)(m0 + ar0) * KX + kb + ac0 * 8);
        cp_async16(aHi + sw_off(ar1, ac1), g_Xhi + (size_t)(m0 + ar1) * KX + kb + ac1 * 8);
        cp_async16(aLo + sw_off(ar1, ac1), g_Xlo + (size_t)(m0 + ar1) * KX + kb + ac1 * 8);
        cp_async16(bHi + sw_off(br, bcc),  g_Whi + (size_t)(n0 + br) * KX + kb + bcc * 8);
        cp_async16(bLo + sw_off(br, bcc),  g_Wlo + (size_t)(n0 + br) * KX + kb + bcc * 8);
    };

    float acc[2][4][4] = {};

    load_stage(0, 0);
    cp_commit();

    const int NIT = KX / 32;   // 64
    for (int it = 0; it < NIT; ++it) {
        if (it + 1 < NIT) load_stage((it + 1) & 1, (it + 1) * 32);
        cp_commit();
        cp_wait1();
        __syncthreads();

        const int s = it & 1;
        const uint32_t aHi = A_HI + s * 8192, aLo = A_LO + s * 8192;
        const uint32_t bHi = B_HI + s * 4096, bLo = B_LO + s * 4096;

        #pragma unroll
        for (int ks = 0; ks < 2; ++ks) {
            uint32_t ahi[2][4], alo[2][4], bhi[2][4], blo[2][4];
            ldsm4(ahi[0], aHi + offA[0][ks]);
            ldsm4(ahi[1], aHi + offA[1][ks]);
            ldsm4(alo[0], aLo + offA[0][ks]);
            ldsm4(alo[1], aLo + offA[1][ks]);
            ldsm4(bhi[0], bHi + offB[0][ks]);
            ldsm4(bhi[1], bHi + offB[1][ks]);
            ldsm4(blo[0], bLo + offB[0][ks]);
            ldsm4(blo[1], bLo + offB[1][ks]);

            #pragma unroll
            for (int mf = 0; mf < 2; ++mf)
                #pragma unroll
                for (int nf = 0; nf < 4; ++nf) {
                    const uint32_t* bh = &bhi[nf >> 1][(nf & 1) * 2];
                    const uint32_t* bl = &blo[nf >> 1][(nf & 1) * 2];
                    mma16816(acc[mf][nf], ahi[mf], bh);   // hi*hi
                    mma16816(acc[mf][nf], ahi[mf], bl);   // hi*lo
                    mma16816(acc[mf][nf], alo[mf], bh);   // lo*hi
                }
        }
        __syncthreads();
    }

    // epilogue: bias + relu
    #pragma unroll
    for (int mf = 0; mf < 2; ++mf) {
        const int m = m0 + wm * 32 + mf * 16 + (l >> 2);
        #pragma unroll
        for (int nf = 0; nf < 4; ++nf) {
            const int n = n0 + wn * 32 + nf * 8 + (l & 3) * 2;
            const float2 bb = *reinterpret_cast<const float2*>(g_bcomb + n);
            float2 o0, o1;
            o0.x = fmaxf(acc[mf][nf][0] + bb.x, 0.f);
            o0.y = fmaxf(acc[mf][nf][1] + bb.y, 0.f);
            o1.x = fmaxf(acc[mf][nf][2] + bb.x, 0.f);
            o1.y = fmaxf(acc[mf][nf][3] + bb.y, 0.f);
            *reinterpret_cast<float2*>(out + (size_t)m * DIM + n)       = o0;
            *reinterpret_cast<float2*>(out + (size_t)(m + 8) * DIM + n) = o1;
        }
    }
}

// ---------------------------------------------------------------------------
extern "C" void kernel_launch(void* const* d_in, const int* in_sizes, int n_in,
                              void* d_out, int out_size)
{
    const float* input_text = (const float*)d_in[0];
    const float* input_img  = (const float*)d_in[1];
    const float* btxt       = (const float*)d_in[2];
    const float* bimg       = (const float*)d_in[3];
    const float* W_user     = (const float*)d_in[4];
    const float* b_user     = (const float*)d_in[5];
    const float* W_l_img    = (const float*)d_in[6];
    const float* b_l_img    = (const float*)d_in[7];
    const float* W_r_img    = (const float*)d_in[8];
    const float* W_l_txt    = (const float*)d_in[9];
    const float* b_l_txt    = (const float*)d_in[10];
    const float* W_r_txt    = (const float*)d_in[11];
    float* out = (float*)d_out;

    k_pre<<<2178, 256>>>(input_text, input_img, btxt, bimg,
                         W_r_img, W_r_txt, W_user, b_user, b_l_img, b_l_txt);
    k_wpack<<<1024, 256>>>(W_l_img, W_l_txt);
    k_gemm_tc<<<dim3(8, 16), 256>>>(out);
}

// round 3
// speedup vs baseline: 1.7226x; 1.1730x over previous
#include <cuda_runtime.h>
#include <cuda_bf16.h>
#include <cstdint>

static constexpr int BATCH = 2048;   // B
static constexpr int NODES = 128;    // M
static constexpr int DIM   = 512;    // D == H
static constexpr int KX    = 2048;   // packed X cols: [img_mean|txt_mean|it|ii]

// grid partition for k_pre
static constexpr int N_WCOMB = 128;                 // bx [0,128)
static constexpr int N_BCOMB = 2;                   // bx [128,130)
static constexpr int N_PACK  = 64;                  // bx [130,194)
static constexpr int N_MEAN  = 512;                 // bx [194,706), 4 rows each
static constexpr int GRID_PRE = N_WCOMB + N_BCOMB + N_PACK + N_MEAN;

// Scratch (static __device__ globals — allocation-free)
__device__ __nv_bfloat16 g_Xhi[(size_t)BATCH * KX];   // 8 MB
__device__ __nv_bfloat16 g_Xlo[(size_t)BATCH * KX];   // 8 MB
__device__ __nv_bfloat16 g_Whi[(size_t)DIM * KX];     // 2 MB
__device__ __nv_bfloat16 g_Wlo[(size_t)DIM * KX];     // 2 MB
__device__ float g_bcomb[DIM];

// ---------------------------------------------------------------------------
// helpers
// ---------------------------------------------------------------------------
__device__ __forceinline__ void split_store4(__nv_bfloat16* hiP, __nv_bfloat16* loP,
                                             size_t idx, float4 v)
{
    union U { __nv_bfloat16 b[4]; uint2 u; } hu, lu;
    float f[4] = {v.x, v.y, v.z, v.w};
    #pragma unroll
    for (int i = 0; i < 4; ++i) {
        __nv_bfloat16 h = __float2bfloat16(f[i]);
        hu.b[i] = h;
        lu.b[i] = __float2bfloat16(f[i] - __bfloat162float(h));
    }
    *reinterpret_cast<uint2*>(hiP + idx) = hu.u;
    *reinterpret_cast<uint2*>(loP + idx) = lu.u;
}

__device__ __forceinline__ uint32_t sw_off(int r, int c) {
    // 32-bf16 rows (64B); 16B chunk swizzle: c' = c ^ ((r>>1)&3)
    return (uint32_t)(r * 64 + ((c ^ ((r >> 1) & 3)) << 4));
}

__device__ __forceinline__ void cp_async16(uint32_t dst, const void* src) {
    asm volatile("cp.async.cg.shared.global [%0], [%1], 16;\n" :: "r"(dst), "l"(src));
}
__device__ __forceinline__ void cp_commit() { asm volatile("cp.async.commit_group;\n"); }
__device__ __forceinline__ void cp_wait1()  { asm volatile("cp.async.wait_group 1;\n"); }

__device__ __forceinline__ void ldsm4(uint32_t* r, uint32_t addr) {
    asm volatile("ldmatrix.sync.aligned.m8n8.x4.shared.b16 {%0,%1,%2,%3}, [%4];\n"
                 : "=r"(r[0]), "=r"(r[1]), "=r"(r[2]), "=r"(r[3]) : "r"(addr));
}
__device__ __forceinline__ void mma16816(float* c, const uint32_t* a, const uint32_t* b) {
    asm volatile("mma.sync.aligned.m16n8k16.row.col.f32.bf16.bf16.f32 "
                 "{%0,%1,%2,%3}, {%4,%5,%6,%7}, {%8,%9}, {%0,%1,%2,%3};\n"
                 : "+f"(c[0]), "+f"(c[1]), "+f"(c[2]), "+f"(c[3])
                 : "r"(a[0]), "r"(a[1]), "r"(a[2]), "r"(a[3]), "r"(b[0]), "r"(b[1]));
}

// ---------------------------------------------------------------------------
// Kernel 1 (fused). Weight-prep CTAs FIRST (hide under the stream),
// persistent mean CTAs after (4 contiguous batch rows each).
// ---------------------------------------------------------------------------
__global__ void __launch_bounds__(256) k_pre(
    const float* __restrict__ itex, const float* __restrict__ iimg,
    const float* __restrict__ btxt, const float* __restrict__ bimg,
    const float* __restrict__ Wri,  const float* __restrict__ Wrt,
    const float* __restrict__ Wu,   const float* __restrict__ bu,
    const float* __restrict__ bli,  const float* __restrict__ blt,
    const float* __restrict__ Wli,  const float* __restrict__ Wlt)
{
    __shared__ float As[16][68];
    __shared__ float Bs[16][64];
    __shared__ float bs[512];

    const int bx  = blockIdx.x;
    const int tid = threadIdx.x;

    if (bx < N_WCOMB) {
        // ---- W_comb tile: (Wri+Wrt)[512x512] @ Wu[512x1024] -> bf16 hi/lo
        //      written straight into g_Whi/g_Wlo columns [1024,2048) ----
        const int n0 = (bx & 15) * 64;     // over 1024 cols
        const int m0 = (bx >> 4) * 64;     // over 512 rows
        const int tx = tid & 15, ty = tid >> 4;
        const int arow = tid >> 2, ac = (tid & 3) * 4;
        const int brow = tid >> 4, bc = (tid & 15) * 4;

        float acc[4][4] = {};
        float4 ra, rb;
        {
            float4 x = *reinterpret_cast<const float4*>(Wri + (m0 + arow) * 512 + ac);
            float4 y = *reinterpret_cast<const float4*>(Wrt + (m0 + arow) * 512 + ac);
            ra = make_float4(x.x + y.x, x.y + y.y, x.z + y.z, x.w + y.w);
            rb = *reinterpret_cast<const float4*>(Wu + brow * 1024 + n0 + bc);
        }
        for (int kt = 0; kt < 32; ++kt) {
            As[ac + 0][arow] = ra.x; As[ac + 1][arow] = ra.y;
            As[ac + 2][arow] = ra.z; As[ac + 3][arow] = ra.w;
            *reinterpret_cast<float4*>(&Bs[brow][bc]) = rb;
            __syncthreads();
            if (kt < 31) {
                const int h0 = (kt + 1) * 16;
                float4 x = *reinterpret_cast<const float4*>(Wri + (m0 + arow) * 512 + h0 + ac);
                float4 y = *reinterpret_cast<const float4*>(Wrt + (m0 + arow) * 512 + h0 + ac);
                ra = make_float4(x.x + y.x, x.y + y.y, x.z + y.z, x.w + y.w);
                rb = *reinterpret_cast<const float4*>(Wu + (h0 + brow) * 1024 + n0 + bc);
            }
            #pragma unroll
            for (int kk = 0; kk < 16; ++kk) {
                float4 a = *reinterpret_cast<const float4*>(&As[kk][ty * 4]);
                float4 b = *reinterpret_cast<const float4*>(&Bs[kk][tx * 4]);
                acc[0][0] += a.x*b.x; acc[0][1] += a.x*b.y; acc[0][2] += a.x*b.z; acc[0][3] += a.x*b.w;
                acc[1][0] += a.y*b.x; acc[1][1] += a.y*b.y; acc[1][2] += a.y*b.z; acc[1][3] += a.y*b.w;
                acc[2][0] += a.z*b.x; acc[2][1] += a.z*b.y; acc[2][2] += a.z*b.z; acc[2][3] += a.z*b.w;
                acc[3][0] += a.w*b.x; acc[3][1] += a.w*b.y; acc[3][2] += a.w*b.z; acc[3][3] += a.w*b.w;
            }
            __syncthreads();
        }
        #pragma unroll
        for (int rr = 0; rr < 4; ++rr) {
            float4 o = make_float4(acc[rr][0], acc[rr][1], acc[rr][2], acc[rr][3]);
            split_store4(g_Whi, g_Wlo,
                         (size_t)(m0 + ty * 4 + rr) * KX + 1024 + n0 + tx * 4, o);
        }
        return;
    }

    if (bx < N_WCOMB + N_BCOMB) {
        // ---- b_comb[n] = bli+blt + (Wri+Wrt)[n,:] . b_user ----
        bs[tid] = bu[tid];
        bs[tid + 256] = bu[tid + 256];
        __syncthreads();
        const int n = (bx - N_WCOMB) * 256 + tid;
        const float4* p1 = reinterpret_cast<const float4*>(Wri + n * 512);
        const float4* p2 = reinterpret_cast<const float4*>(Wrt + n * 512);
        float acc = 0.f;
        #pragma unroll 4
        for (int h4 = 0; h4 < 128; ++h4) {
            float4 a = p1[h4], b = p2[h4];
            const float* bb = bs + h4 * 4;
            acc += (a.x + b.x) * bb[0] + (a.y + b.y) * bb[1]
                 + (a.z + b.z) * bb[2] + (a.w + b.w) * bb[3];
        }
        g_bcomb[n] = acc + bli[n] + blt[n];
        return;
    }

    if (bx < N_WCOMB + N_BCOMB + N_PACK) {
        // ---- pack [Wli | Wlt] -> g_Whi/g_Wlo columns [0,1024) ----
        // 512 rows x 256 float4-chunks = 131072 items; 64 CTAs x 8 iters x 256 thr
        const int base = (bx - N_WCOMB - N_BCOMB) * 256 * 8;
        #pragma unroll
        for (int it = 0; it < 8; ++it) {
            const int id = base + it * 256 + tid;
            const int n  = id >> 8;           // 0..511
            const int k  = (id & 255) * 4;    // 0..1020
            float4 v;
            if (k < 512) v = *reinterpret_cast<const float4*>(Wli + n * 512 + k);
            else         v = *reinterpret_cast<const float4*>(Wlt + n * 512 + (k - 512));
            split_store4(g_Whi, g_Wlo, (size_t)n * KX + k, v);
        }
        return;
    }

    // ---- mean + pack X (bf16 hi/lo): persistent, 4 contiguous rows per CTA ----
    {
        const int widx = bx - (N_WCOMB + N_BCOMB + N_PACK);   // 0..511
        const bool lo  = (tid < 128);
        const int chunk = lo ? tid : (tid - 128);             // float4 chunk over H=512
        const int xoff  = lo ? 0 : 512;
        const int xoff2 = lo ? 1024 : 1536;
        const float* srcM = lo ? bimg : btxt;
        const float* srcP = lo ? itex : iimg;
        const float s = 1.0f / (float)NODES;

        #pragma unroll 1
        for (int r = 0; r < 4; ++r) {
            const int b = widx * 4 + r;
            const float4* p = reinterpret_cast<const float4*>(
                                  srcM + (size_t)b * NODES * DIM) + chunk;
            float4 acc = make_float4(0.f, 0.f, 0.f, 0.f);
            #pragma unroll 16
            for (int m = 0; m < NODES; ++m) {
                float4 v = __ldcs(p + (size_t)m * (DIM / 4));
                acc.x += v.x; acc.y += v.y; acc.z += v.z; acc.w += v.w;
            }
            acc.x *= s; acc.y *= s; acc.z *= s; acc.w *= s;
            split_store4(g_Xhi, g_Xlo, (size_t)b * KX + xoff + chunk * 4, acc);

            float4 pv = reinterpret_cast<const float4*>(srcP + (size_t)b * DIM)[chunk];
            split_store4(g_Xhi, g_Xlo, (size_t)b * KX + xoff2 + chunk * 4, pv);
        }
    }
}

// ---------------------------------------------------------------------------
// Kernel 2: out = relu(X @ W_all^T + b_comb), bf16 3-term split, tensor cores.
// CTA 128(M) x 64(N), KBLK=32, 8 warps (4m x 2n), warp tile 32x32.
// ---------------------------------------------------------------------------
__global__ void __launch_bounds__(256) k_gemm_tc(float* __restrict__ out)
{
    __shared__ __align__(128) unsigned char sm[49152];
    const uint32_t smBase = (uint32_t)__cvta_generic_to_shared(sm);
    const uint32_t A_HI = smBase, A_LO = smBase + 16384;
    const uint32_t B_HI = smBase + 32768, B_LO = smBase + 40960;

    const int tid = threadIdx.x;
    const int l   = tid & 31;
    const int wid = tid >> 5;
    const int wm  = wid >> 1;
    const int wn  = wid & 1;
    const int n0  = blockIdx.x * 64;
    const int m0  = blockIdx.y * 128;

    uint32_t offA[2][2], offB[2][2];
    {
        const int ti = l >> 3;
        #pragma unroll
        for (int f = 0; f < 2; ++f)
            #pragma unroll
            for (int ks = 0; ks < 2; ++ks) {
                int tm = wm * 32 + f * 16 + (ti & 1) * 8 + (l & 7);
                int tc = ks * 2 + (ti >> 1);
                offA[f][ks] = (uint32_t)(tm * 64 + ((tc ^ ((tm >> 1) & 3)) << 4));
            }
        #pragma unroll
        for (int q = 0; q < 2; ++q)
            #pragma unroll
            for (int ks = 0; ks < 2; ++ks) {
                int tn = wn * 32 + q * 16 + (ti >> 1) * 8 + (l & 7);
                int tc = ks * 2 + (ti & 1);
                offB[q][ks] = (uint32_t)(tn * 64 + ((tc ^ ((tn >> 1) & 3)) << 4));
            }
    }

    const int ar0 = tid >> 2,         ac0 = tid & 3;
    const int ar1 = (tid + 256) >> 2, ac1 = tid & 3;
    const int br  = tid >> 2,         bcc = tid & 3;

    auto load_stage = [&](int s, int kb) {
        const uint32_t aHi = A_HI + s * 8192, aLo = A_LO + s * 8192;
        const uint32_t bHi = B_HI + s * 4096, bLo = B_LO + s * 4096;
        cp_async16(aHi + sw_off(ar0, ac0), g_Xhi + (size_t)(m0 + ar0) * KX + kb + ac0 * 8);
        cp_async16(aLo + sw_off(ar0, ac0), g_Xlo + (size_t)(m0 + ar0) * KX + kb + ac0 * 8);
        cp_async16(aHi + sw_off(ar1, ac1), g_Xhi + (size_t)(m0 + ar1) * KX + kb + ac1 * 8);
        cp_async16(aLo + sw_off(ar1, ac1), g_Xlo + (size_t)(m0 + ar1) * KX + kb + ac1 * 8);
        cp_async16(bHi + sw_off(br, bcc),  g_Whi + (size_t)(n0 + br) * KX + kb + bcc * 8);
        cp_async16(bLo + sw_off(br, bcc),  g_Wlo + (size_t)(n0 + br) * KX + kb + bcc * 8);
    };

    float acc[2][4][4] = {};

    load_stage(0, 0);
    cp_commit();

    const int NIT = KX / 32;   // 64
    for (int it = 0; it < NIT; ++it) {
        if (it + 1 < NIT) load_stage((it + 1) & 1, (it + 1) * 32);
        cp_commit();
        cp_wait1();
        __syncthreads();

        const int s = it & 1;
        const uint32_t aHi = A_HI + s * 8192, aLo = A_LO + s * 8192;
        const uint32_t bHi = B_HI + s * 4096, bLo = B_LO + s * 4096;

        #pragma unroll
        for (int ks = 0; ks < 2; ++ks) {
            uint32_t ahi[2][4], alo[2][4], bhi[2][4], blo[2][4];
            ldsm4(ahi[0], aHi + offA[0][ks]);
            ldsm4(ahi[1], aHi + offA[1][ks]);
            ldsm4(alo[0], aLo + offA[0][ks]);
            ldsm4(alo[1], aLo + offA[1][ks]);
            ldsm4(bhi[0], bHi + offB[0][ks]);
            ldsm4(bhi[1], bHi + offB[1][ks]);
            ldsm4(blo[0], bLo + offB[0][ks]);
            ldsm4(blo[1], bLo + offB[1][ks]);

            #pragma unroll
            for (int mf = 0; mf < 2; ++mf)
                #pragma unroll
                for (int nf = 0; nf < 4; ++nf) {
                    const uint32_t* bh = &bhi[nf >> 1][(nf & 1) * 2];
                    const uint32_t* bl = &blo[nf >> 1][(nf & 1) * 2];
                    mma16816(acc[mf][nf], ahi[mf], bh);
                    mma16816(acc[mf][nf], ahi[mf], bl);
                    mma16816(acc[mf][nf], alo[mf], bh);
                }
        }
        __syncthreads();
    }

    #pragma unroll
    for (int mf = 0; mf < 2; ++mf) {
        const int m = m0 + wm * 32 + mf * 16 + (l >> 2);
        #pragma unroll
        for (int nf = 0; nf < 4; ++nf) {
            const int n = n0 + wn * 32 + nf * 8 + (l & 3) * 2;
            const float2 bb = *reinterpret_cast<const float2*>(g_bcomb + n);
            float2 o0, o1;
            o0.x = fmaxf(acc[mf][nf][0] + bb.x, 0.f);
            o0.y = fmaxf(acc[mf][nf][1] + bb.y, 0.f);
            o1.x = fmaxf(acc[mf][nf][2] + bb.x, 0.f);
            o1.y = fmaxf(acc[mf][nf][3] + bb.y, 0.f);
            *reinterpret_cast<float2*>(out + (size_t)m * DIM + n)       = o0;
            *reinterpret_cast<float2*>(out + (size_t)(m + 8) * DIM + n) = o1;
        }
    }
}

// ---------------------------------------------------------------------------
extern "C" void kernel_launch(void* const* d_in, const int* in_sizes, int n_in,
                              void* d_out, int out_size)
{
    const float* input_text = (const float*)d_in[0];
    const float* input_img  = (const float*)d_in[1];
    const float* btxt       = (const float*)d_in[2];
    const float* bimg       = (const float*)d_in[3];
    const float* W_user     = (const float*)d_in[4];
    const float* b_user     = (const float*)d_in[5];
    const float* W_l_img    = (const float*)d_in[6];
    const float* b_l_img    = (const float*)d_in[7];
    const float* W_r_img    = (const float*)d_in[8];
    const float* W_l_txt    = (const float*)d_in[9];
    const float* b_l_txt    = (const float*)d_in[10];
    const float* W_r_txt    = (const float*)d_in[11];
    float* out = (float*)d_out;

    k_pre<<<GRID_PRE, 256>>>(input_text, input_img, btxt, bimg,
                             W_r_img, W_r_txt, W_user, b_user, b_l_img, b_l_txt,
                             W_l_img, W_l_txt);
    k_gemm_tc<<<dim3(8, 16), 256>>>(out);
}